// round 8
// baseline (speedup 1.0000x reference)
#include <cuda_runtime.h>
#include <cstdint>

#define NTOK   65536
#define DIMC   256
#define NCODE  1024
#define HWSZ   4096
#define ZSZ    16777216
#define OFF_ZQ      1
#define OFF_PERP    16777217
#define OFF_MINENC  16777218ULL
#define OFF_IDX     83886082ULL

#define TOKT   128
#define MARGIN 1.2e-2f
#define CAP    24

// quantization constants
#define SZQ  19.538461538f      /* 127/6.5  (z scale)  */
#define SEQ  130048.0f          /* 1024*127 (e scale)  */

// smem byte offsets (dynamic)
#define O_A8    0          // [64 k4][128 tok] int32 = 32768
#define O_BS    32768      // 2 x [64 k4][128 code] int32 = 65536
#define O_EN    98304      // 1024 f32 = 4096
#define O_SBEST 102400     // 128 u32
#define O_SCNT  102912     // 128 i32
#define O_SCAND 103424     // 128*24 i32 = 12288
#define SMEM_BYTES 115712

// ---------------- scratch ----------------
__device__ float    g_et[DIMC * NCODE];     // [c][k] for k_epi gather
__device__ uint32_t g_e8[64 * NCODE];       // [k4][code] packed int8 (dims 4k4..4k4+3)
__device__ float    g_en[NCODE];
__device__ int      g_idx[NTOK];
__device__ int      g_hist[NCODE];
__device__ double   g_loss;

__device__ __forceinline__ unsigned fenc(float f) {
    unsigned u = __float_as_uint(f);
    return (u & 0x80000000u) ? ~u : (u | 0x80000000u);
}
__device__ __forceinline__ float fdec(unsigned e) {
    unsigned u = (e & 0x80000000u) ? (e & 0x7FFFFFFFu) : ~e;
    return __uint_as_float(u);
}
#define ENC_FLT_MAX 0xFF7FFFFFu   /* fenc(3.402823e38f) */

__device__ __forceinline__ int q8z(float x) {
    int v = __float2int_rn(x * SZQ);
    v = v > 127 ? 127 : v;
    v = v < -127 ? -127 : v;
    return v & 0xff;
}

#define CPA16(dst, src) \
    asm volatile("cp.async.cg.shared.global [%0], [%1], 16;" :: "r"(dst), "l"(src))
#define CPA_COMMIT() asm volatile("cp.async.commit_group;")
#define CPA_WAIT(n)  asm volatile("cp.async.wait_group %0;" :: "n"(n))

// ---------------- pass1: dp4a int8 screen + exact fp32 re-rank ----------------
__global__ void __launch_bounds__(512, 1) k_pass1(const float* __restrict__ z,
                                                  const float* __restrict__ embed) {
    extern __shared__ char sm[];
    int*      A8    = (int*)(sm + O_A8);
    int*      BS    = (int*)(sm + O_BS);
    float*    EN    = (float*)(sm + O_EN);
    unsigned* sbest = (unsigned*)(sm + O_SBEST);
    int*      scnt  = (int*)(sm + O_SCNT);
    int*      scand = (int*)(sm + O_SCAND);

    const uint32_t bs_s = (uint32_t)__cvta_generic_to_shared(BS);
    const float lam = 2.0f * (6.5f / 127.0f) / SEQ;   // dp scale for int dot

    int tid = threadIdx.x;
    int tx  = tid & 15;          // code group: 8 codes
    int ty  = tid >> 4;          // token group: 4 tokens (ty in [0,32))
    int n0  = blockIdx.x * TOKT;
    int b   = n0 >> 12, hw0 = n0 & 4095;
    const float* zb = z + (size_t)b * (DIMC * HWSZ) + hw0;

    // ---- issue cp.async for B tile 0 (32 KB, 2048 x 16B) ----
    {
        const char* src = (const char*)g_e8;
#pragma unroll
        for (int j = 0; j < 4; j++) {
            int u = tid + j * 512;
            int k4 = u >> 5, c16 = u & 31;
            CPA16(bs_s + (uint32_t)(k4 * 512 + c16 * 16),
                  src + (size_t)k4 * 4096 + c16 * 16);
        }
        CPA_COMMIT();
    }

    // ---- init smem ----
    if (tid < 128) { sbest[tid] = ENC_FLT_MAX; scnt[tid] = 0; }
    for (int i = tid; i < NCODE; i += 512) EN[i] = g_en[i];

    // ---- quantize+pack A8[k4][tok] once (coalesced over tok) ----
#pragma unroll
    for (int j = 0; j < 16; j++) {
        int u = tid + j * 512;                // 8192 entries
        int tok = u & 127, k4 = u >> 7;
        const float* zp = zb + (size_t)(4 * k4) * HWSZ + tok;
        int q0 = q8z(zp[0]);
        int q1 = q8z(zp[(size_t)HWSZ]);
        int q2 = q8z(zp[(size_t)2 * HWSZ]);
        int q3 = q8z(zp[(size_t)3 * HWSZ]);
        A8[k4 * 128 + tok] = q0 | (q1 << 8) | (q2 << 16) | (q3 << 24);
    }

    CPA_WAIT(0);
    __syncthreads();

    for (int T = 0; T < 8; T++) {
        int buf = T & 1;
        // prefetch tile T+1 into other buffer (prev compute on it is done)
        if (T < 7) {
            const char* src = (const char*)g_e8 + (size_t)(T + 1) * 512;
            uint32_t dst = bs_s + (uint32_t)((1 - buf) * 32768);
#pragma unroll
            for (int j = 0; j < 4; j++) {
                int u = tid + j * 512;
                int k4 = u >> 5, c16 = u & 31;
                CPA16(dst + (uint32_t)(k4 * 512 + c16 * 16),
                      src + (size_t)k4 * 4096 + c16 * 16);
            }
            CPA_COMMIT();
            CPA_WAIT(1);
        } else {
            CPA_WAIT(0);
        }
        __syncthreads();

        // ---- compute: 64 k4 steps (full K=256), exact int32 accumulation ----
        int acc[4][8];
#pragma unroll
        for (int i = 0; i < 4; i++)
#pragma unroll
            for (int j = 0; j < 8; j++) acc[i][j] = 0;

        const int* ap = A8 + ty * 4;
        const int* bp = BS + buf * 8192 + tx * 8;

#pragma unroll 8
        for (int k4 = 0; k4 < 64; k4++) {
            int a4[4], b8[8];
            *(int4*)a4       = *(const int4*)(ap + k4 * 128);
            *(int4*)b8       = *(const int4*)(bp + k4 * 128);
            *(int4*)(b8 + 4) = *(const int4*)(bp + k4 * 128 + 4);
#pragma unroll
            for (int i = 0; i < 4; i++)
#pragma unroll
                for (int j = 0; j < 8; j++)
                    acc[i][j] = __dp4a(a4[i], b8[j], acc[i][j]);
        }

        // ---- phase A: settle per-row running min ----
#pragma unroll
        for (int i = 0; i < 4; i++) {
            float rm = 3.4e38f;
#pragma unroll
            for (int j = 0; j < 8; j++) {
                float dp = EN[T * 128 + tx * 8 + j] - lam * (float)acc[i][j];
                if (dp < rm) rm = dp;
            }
            atomicMin(&sbest[ty * 4 + i], fenc(rm));
        }
        __syncthreads();

        // ---- phase B: push candidates against settled threshold ----
#pragma unroll
        for (int i = 0; i < 4; i++) {
            int row = ty * 4 + i;
            float thr = fdec(sbest[row]) + MARGIN;
#pragma unroll
            for (int j = 0; j < 8; j++) {
                int code = T * 128 + tx * 8 + j;
                float dp = EN[code] - lam * (float)acc[i][j];
                if (dp < thr) {
                    int pos = atomicAdd(&scnt[row], 1);
                    if (pos < CAP) scand[row * CAP + pos] = code;
                }
            }
        }
        __syncthreads();
    }

    // ---- exact fp32 re-rank: one token per thread (rows 0..127) ----
    if (tid < TOKT) {
        int row = tid;
        int m = scnt[row];
        if (m >= 1 && m <= CAP) {
            const float* zp = zb + row;
            float zn = 0.0f;
            for (int c = 0; c < DIMC; c++)
                zn = fmaf(zp[(size_t)c * HWSZ], zp[(size_t)c * HWSZ], zn);
            float bestx = 3.4e38f;
            int   besti = 0x7FFFFFFF;
            for (int g0 = 0; g0 < m; g0 += 8) {
                int gc = m - g0; if (gc > 8) gc = 8;
                int codes8[8];
#pragma unroll
                for (int q = 0; q < 8; q++)
                    codes8[q] = scand[row * CAP + g0 + (q < gc ? q : 0)];
                float dot[8];
#pragma unroll
                for (int q = 0; q < 8; q++) dot[q] = 0.0f;
                for (int c = 0; c < DIMC; c++) {
                    float zc = zp[(size_t)c * HWSZ];
#pragma unroll
                    for (int q = 0; q < 8; q++)
                        dot[q] = fmaf(zc, __ldg(&embed[(size_t)codes8[q] * DIMC + c]), dot[q]);
                }
#pragma unroll
                for (int q = 0; q < 8; q++) {
                    if (q < gc) {
                        int code = codes8[q];
                        float v = (zn + EN[code]) - 2.0f * dot[q];
                        if (v < bestx || (v == bestx && code < besti)) {
                            bestx = v; besti = code;
                        }
                    }
                }
            }
            g_idx[n0 + row] = besti;
        }
    }
    __syncthreads();

    // ---- fallback: warp-cooperative exact full scan (overflow/empty, rare) ----
    {
        int wz = tid >> 5, lane = tid & 31;
        for (int r = wz; r < TOKT; r += 16) {
            int m = scnt[r];
            if (m > CAP || m == 0) {
                const float* zp = zb + r;
                float zn = 0.0f;
                for (int c = 0; c < DIMC; c++)
                    zn = fmaf(zp[(size_t)c * HWSZ], zp[(size_t)c * HWSZ], zn);
                float bvv = 3.4e38f; int bii = 0x7FFFFFFF;
                for (int code = lane; code < NCODE; code += 32) {
                    float dot = 0.0f;
                    for (int c = 0; c < DIMC; c++)
                        dot = fmaf(zp[(size_t)c * HWSZ],
                                   __ldg(&embed[(size_t)code * DIMC + c]), dot);
                    float v = (zn + EN[code]) - 2.0f * dot;
                    if (v < bvv) { bvv = v; bii = code; }
                }
#pragma unroll
                for (int o = 16; o; o >>= 1) {
                    float ov = __shfl_xor_sync(0xffffffffu, bvv, o);
                    int   oi = __shfl_xor_sync(0xffffffffu, bii, o);
                    if (ov < bvv || (ov == bvv && oi < bii)) { bvv = ov; bii = oi; }
                }
                if (lane == 0) g_idx[n0 + r] = bii;
            }
        }
    }
}

// ---------------- embed prep: transpose + int8 pack + |e|^2 + zero accum ----------------
__global__ void k_prep(const float* __restrict__ e) {
    int k = blockIdx.x;
    int t = threadIdx.x;                       // 64 threads, 4 dims each
    float4 v = ((const float4*)(e + (size_t)k * DIMC))[t];
    int c = t * 4;
    g_et[(c + 0) * NCODE + k] = v.x;
    g_et[(c + 1) * NCODE + k] = v.y;
    g_et[(c + 2) * NCODE + k] = v.z;
    g_et[(c + 3) * NCODE + k] = v.w;
    int q0 = __float2int_rn(v.x * SEQ) & 0xff;
    int q1 = __float2int_rn(v.y * SEQ) & 0xff;
    int q2 = __float2int_rn(v.z * SEQ) & 0xff;
    int q3 = __float2int_rn(v.w * SEQ) & 0xff;
    g_e8[t * NCODE + k] = (uint32_t)(q0 | (q1 << 8) | (q2 << 16) | (q3 << 24));
    float s = v.x * v.x + v.y * v.y + v.z * v.z + v.w * v.w;
#pragma unroll
    for (int o = 16; o; o >>= 1) s += __shfl_down_sync(0xffffffffu, s, o);
    __shared__ float sh[2];
    if ((t & 31) == 0) sh[t >> 5] = s;
    __syncthreads();
    if (t == 0) {
        g_en[k]   = sh[0] + sh[1];
        g_hist[k] = 0;
        if (k == 0) g_loss = 0.0;
    }
}

// ---------------- z_q gather (vectorized) + loss ----------------
__global__ void k_epi(const float* __restrict__ z, float* __restrict__ out) {
    int i4  = blockIdx.x * 256 + threadIdx.x;      // over ZSZ/4
    int hw4 = i4 & 1023;
    int c   = (i4 >> 10) & 255;
    int b   = i4 >> 18;
    int4 kk = *(const int4*)(g_idx + (b << 12) + (hw4 << 2));
    float4 zv = ((const float4*)z)[i4];
    const float* row = g_et + c * NCODE;
    float dx = __ldg(&row[kk.x]) - zv.x;
    float dy = __ldg(&row[kk.y]) - zv.y;
    float dz = __ldg(&row[kk.z]) - zv.z;
    float dw = __ldg(&row[kk.w]) - zv.w;
    size_t o = OFF_ZQ + (size_t)i4 * 4;
    out[o + 0] = zv.x + dx;
    out[o + 1] = zv.y + dy;
    out[o + 2] = zv.z + dz;
    out[o + 3] = zv.w + dw;
    float s = dx * dx + dy * dy + dz * dz + dw * dw;
#pragma unroll
    for (int of = 16; of; of >>= 1) s += __shfl_down_sync(0xffffffffu, s, of);
    __shared__ float red[8];
    int t = threadIdx.x;
    if ((t & 31) == 0) red[t >> 5] = s;
    __syncthreads();
    if (t < 8) {
        float w = red[t];
#pragma unroll
        for (int of = 4; of; of >>= 1) w += __shfl_down_sync(0x000000ffu, w, of);
        if (t == 0) atomicAdd(&g_loss, (double)w);
    }
}

// ---------------- one-hot scatter + idx + histogram ----------------
__global__ void k_scat(float* __restrict__ out) {
    int n = blockIdx.x * 256 + threadIdx.x;
    int k = g_idx[n];
    out[OFF_MINENC + (size_t)n * NCODE + k] = 1.0f;
    out[OFF_IDX + n] = (float)k;
    atomicAdd(&g_hist[k], 1);
}

// ---------------- finalize ----------------
__global__ void k_fin(float* __restrict__ out) {
    int t = threadIdx.x;
    float em = (float)g_hist[t] * (1.0f / 65536.0f);
    float v = em * logf(em + 1e-10f);
    __shared__ float sh[32];
#pragma unroll
    for (int o = 16; o; o >>= 1) v += __shfl_down_sync(0xffffffffu, v, o);
    if ((t & 31) == 0) sh[t >> 5] = v;
    __syncthreads();
    if (t < 32) {
        float w = sh[t];
#pragma unroll
        for (int o = 16; o; o >>= 1) w += __shfl_down_sync(0xffffffffu, w, o);
        if (t == 0) {
            out[OFF_PERP] = expf(-w);
            out[0] = (float)(g_loss * (1.25 / 16777216.0));
        }
    }
}

// ---------------- launch ----------------
extern "C" void kernel_launch(void* const* d_in, const int* in_sizes, int n_in,
                              void* d_out, int out_size) {
    const float* z = (const float*)d_in[0];
    const float* e = (const float*)d_in[1];
    float* out = (float*)d_out;
    (void)in_sizes; (void)n_in; (void)out_size;

    static int attr_set = 0;
    if (!attr_set) {
        cudaFuncSetAttribute(k_pass1, cudaFuncAttributeMaxDynamicSharedMemorySize, SMEM_BYTES);
        attr_set = 1;
    }

    k_prep  <<<NCODE, 64>>>(e);
    k_pass1 <<<NTOK / TOKT, 512, SMEM_BYTES>>>(z, e);
    cudaMemsetAsync(out + OFF_MINENC, 0, 268435456ULL);
    k_epi   <<<ZSZ / 1024, 256>>>(z, out);
    k_scat  <<<NTOK / 256, 256>>>(out);
    k_fin   <<<1, 1024>>>(out);
}

// round 9
// speedup vs baseline: 14.2464x; 14.2464x over previous
#include <cuda_runtime.h>
#include <cstdint>

#define NTOK   65536
#define DIMC   256
#define NCODE  1024
#define HWSZ   4096
#define ZSZ    16777216
#define OFF_ZQ      1
#define OFF_PERP    16777217
#define OFF_MINENC  16777218ULL
#define OFF_IDX     83886082ULL

// smem byte offsets (dynamic)
#define O_AS    0          // [256 k][128 tok] f32 = 131072
#define O_BS    131072     // 2 x [32 k][256 code] f32 = 65536
#define O_EN    196608     // 1024 f32 = 4096
#define SMEM_BYTES 200704

// ---------------- scratch ----------------
__device__ float  g_et[DIMC * NCODE];     // [c][k]: embed transposed (K-major)
__device__ float  g_en[NCODE];
__device__ float  g_zn[NTOK];
__device__ int    g_idx[NTOK];
__device__ int    g_hist[NCODE];
__device__ double g_loss;

#define CPA16(dst, src) \
    asm volatile("cp.async.cg.shared.global [%0], [%1], 16;" :: "r"(dst), "l"(src))
#define CPA_COMMIT() asm volatile("cp.async.commit_group;")
#define CPA_WAIT(n)  asm volatile("cp.async.wait_group %0;" :: "n"(n))

// ---------------- k_argmin: direct fp32 FFMA GEMM + argmin ----------------
// 512 threads: tx = tid&31 (8 codes each -> 256 codes/tile), warp = tid>>5
// owns 8 tokens. Block = 128 tokens x 1024 codes, K=256 resident in smem.
__global__ void __launch_bounds__(512, 1) k_argmin(const float* __restrict__ z) {
    extern __shared__ float sm[];
    float* As = sm;                      // As[k][tok], row 128 floats
    float* Bs = sm + (O_BS >> 2);        // Bs[buf][k][code], row 256 floats
    float* EN = sm + (O_EN >> 2);

    const uint32_t bs_s = (uint32_t)__cvta_generic_to_shared(Bs);

    int tid = threadIdx.x;
    int tx  = tid & 31;
    int wp  = tid >> 5;                  // warp id = token group
    int n0  = blockIdx.x * 128;
    int b   = n0 >> 12, hw0 = n0 & 4095;
    const float* zb = z + (size_t)b * (DIMC * HWSZ) + hw0;

    // ---- prefetch B chunk 0 (ct=0, kc=0): 32 rows x 1KB ----
    {
        const char* src = (const char*)g_et;
#pragma unroll
        for (int j = 0; j < 4; j++) {
            int u = tid + j * 512;               // 2048 x 16B
            int k = u >> 6, c16 = u & 63;
            CPA16(bs_s + (uint32_t)(k * 1024 + c16 * 16),
                  src + (size_t)k * 4096 + c16 * 16);
        }
        CPA_COMMIT();
    }

    // ---- load A tile: As[k][tok] for all 256 dims (coalesced over tok) ----
#pragma unroll
    for (int j = 0; j < 16; j++) {
        int u = tid + j * 512;                   // 8192 float4
        int c = u >> 5, t4 = u & 31;
        float4 v = *(const float4*)(zb + (size_t)c * HWSZ + t4 * 4);
        *(float4*)(As + c * 128 + t4 * 4) = v;
    }
    for (int i = tid; i < NCODE; i += 512) EN[i] = g_en[i];

    // per-thread state: 8 tokens (warp's rows) x 8 codes
    float zn[8];
#pragma unroll
    for (int i = 0; i < 8; i++) zn[i] = g_zn[n0 + wp * 8 + i];
    float bv[8];
    int   bi[8];
#pragma unroll
    for (int i = 0; i < 8; i++) { bv[i] = 3.4e38f; bi[i] = 0; }

    CPA_WAIT(0);
    __syncthreads();

    float acc[8][8];

    for (int m = 0; m < 32; m++) {               // m = ct*8 + kc
        int ct = m >> 3, kc = m & 7, buf = m & 1;

        // prefetch next B chunk
        if (m < 31) {
            int nct = (m + 1) >> 3, nkc = (m + 1) & 7;
            const char* src = (const char*)g_et
                            + (size_t)nkc * 32 * 4096 + (size_t)nct * 1024;
            uint32_t dst = bs_s + (uint32_t)((1 - buf) * 32768);
#pragma unroll
            for (int j = 0; j < 4; j++) {
                int u = tid + j * 512;
                int k = u >> 6, c16 = u & 63;
                CPA16(dst + (uint32_t)(k * 1024 + c16 * 16),
                      src + (size_t)k * 4096 + c16 * 16);
            }
            CPA_COMMIT();
        }

        if (kc == 0) {
#pragma unroll
            for (int i = 0; i < 8; i++)
#pragma unroll
                for (int j = 0; j < 8; j++) acc[i][j] = 0.0f;
        }

        // ---- compute: 32 k-steps, 64 FFMA each ----
        const float* ap = As + kc * 32 * 128 + wp * 8;
        const float* bp = Bs + buf * 8192 + tx * 8;
#pragma unroll 4
        for (int k = 0; k < 32; k++) {
            float a[8], bb[8];
            *(float4*)a        = *(const float4*)(ap + k * 128);      // broadcast
            *(float4*)(a + 4)  = *(const float4*)(ap + k * 128 + 4);
            *(float4*)bb       = *(const float4*)(bp + k * 256);
            *(float4*)(bb + 4) = *(const float4*)(bp + k * 256 + 4);
#pragma unroll
            for (int i = 0; i < 8; i++)
#pragma unroll
                for (int j = 0; j < 8; j++)
                    acc[i][j] = fmaf(a[i], bb[j], acc[i][j]);
        }

        // ---- epilogue at end of each code tile ----
        if (kc == 7) {
#pragma unroll
            for (int j = 0; j < 8; j++) {
                int code = ct * 256 + tx * 8 + j;
                float enj = EN[code];
#pragma unroll
                for (int i = 0; i < 8; i++) {
                    float v = (zn[i] + enj) - 2.0f * acc[i][j];
                    if (v < bv[i]) { bv[i] = v; bi[i] = code; }
                }
            }
        }

        if (m < 31) { CPA_WAIT(1); }
        __syncthreads();
    }

    // ---- warp-level argmin across tx lanes (first-index tie-break) ----
#pragma unroll
    for (int i = 0; i < 8; i++) {
        float v = bv[i];
        int   ix = bi[i];
#pragma unroll
        for (int o = 16; o; o >>= 1) {
            float ov = __shfl_xor_sync(0xffffffffu, v, o);
            int   oi = __shfl_xor_sync(0xffffffffu, ix, o);
            if (ov < v || (ov == v && oi < ix)) { v = ov; ix = oi; }
        }
        if (tx == 0) g_idx[n0 + wp * 8 + i] = ix;
    }
}

// ---------------- |z_n|^2 ----------------
__global__ void k_znorm(const float* __restrict__ z) {
    int b  = blockIdx.x >> 4;
    int hw = ((blockIdx.x & 15) << 8) + threadIdx.x;
    const float* p = z + (size_t)b * DIMC * HWSZ + hw;
    float s = 0.0f;
#pragma unroll 8
    for (int c = 0; c < DIMC; c++) {
        float v = p[(size_t)c * HWSZ];
        s = fmaf(v, v, s);
    }
    g_zn[b * HWSZ + hw] = s;
}

// ---------------- embed prep: transpose + |e|^2 + zero accum ----------------
__global__ void k_prep(const float* __restrict__ e) {
    int k = blockIdx.x;
    int t = threadIdx.x;                       // 64 threads, 4 dims each
    float4 v = ((const float4*)(e + (size_t)k * DIMC))[t];
    int c = t * 4;
    g_et[(c + 0) * NCODE + k] = v.x;
    g_et[(c + 1) * NCODE + k] = v.y;
    g_et[(c + 2) * NCODE + k] = v.z;
    g_et[(c + 3) * NCODE + k] = v.w;
    float s = v.x * v.x + v.y * v.y + v.z * v.z + v.w * v.w;
#pragma unroll
    for (int o = 16; o; o >>= 1) s += __shfl_down_sync(0xffffffffu, s, o);
    __shared__ float sh[2];
    if ((t & 31) == 0) sh[t >> 5] = s;
    __syncthreads();
    if (t == 0) {
        g_en[k]   = sh[0] + sh[1];
        g_hist[k] = 0;
        if (k == 0) g_loss = 0.0;
    }
}

// ---------------- z_q gather (vectorized) + loss ----------------
__global__ void k_epi(const float* __restrict__ z, float* __restrict__ out) {
    int i4  = blockIdx.x * 256 + threadIdx.x;      // over ZSZ/4
    int hw4 = i4 & 1023;
    int c   = (i4 >> 10) & 255;
    int b   = i4 >> 18;
    int4 kk = *(const int4*)(g_idx + (b << 12) + (hw4 << 2));
    float4 zv = ((const float4*)z)[i4];
    const float* row = g_et + c * NCODE;
    float dx = __ldg(&row[kk.x]) - zv.x;
    float dy = __ldg(&row[kk.y]) - zv.y;
    float dz = __ldg(&row[kk.z]) - zv.z;
    float dw = __ldg(&row[kk.w]) - zv.w;
    size_t o = OFF_ZQ + (size_t)i4 * 4;
    out[o + 0] = zv.x + dx;
    out[o + 1] = zv.y + dy;
    out[o + 2] = zv.z + dz;
    out[o + 3] = zv.w + dw;
    float s = dx * dx + dy * dy + dz * dz + dw * dw;
#pragma unroll
    for (int of = 16; of; of >>= 1) s += __shfl_down_sync(0xffffffffu, s, of);
    __shared__ float red[8];
    int t = threadIdx.x;
    if ((t & 31) == 0) red[t >> 5] = s;
    __syncthreads();
    if (t < 8) {
        float w = red[t];
#pragma unroll
        for (int of = 4; of; of >>= 1) w += __shfl_down_sync(0x000000ffu, w, of);
        if (t == 0) atomicAdd(&g_loss, (double)w);
    }
}

// ---------------- one-hot scatter + idx + histogram ----------------
__global__ void k_scat(float* __restrict__ out) {
    int n = blockIdx.x * 256 + threadIdx.x;
    int k = g_idx[n];
    out[OFF_MINENC + (size_t)n * NCODE + k] = 1.0f;
    out[OFF_IDX + n] = (float)k;
    atomicAdd(&g_hist[k], 1);
}

// ---------------- finalize ----------------
__global__ void k_fin(float* __restrict__ out) {
    int t = threadIdx.x;
    float em = (float)g_hist[t] * (1.0f / 65536.0f);
    float v = em * logf(em + 1e-10f);
    __shared__ float sh[32];
#pragma unroll
    for (int o = 16; o; o >>= 1) v += __shfl_down_sync(0xffffffffu, v, o);
    if ((t & 31) == 0) sh[t >> 5] = v;
    __syncthreads();
    if (t < 32) {
        float w = sh[t];
#pragma unroll
        for (int o = 16; o; o >>= 1) w += __shfl_down_sync(0xffffffffu, w, o);
        if (t == 0) {
            out[OFF_PERP] = expf(-w);
            out[0] = (float)(g_loss * (1.25 / 16777216.0));
        }
    }
}

// ---------------- launch ----------------
extern "C" void kernel_launch(void* const* d_in, const int* in_sizes, int n_in,
                              void* d_out, int out_size) {
    const float* z = (const float*)d_in[0];
    const float* e = (const float*)d_in[1];
    float* out = (float*)d_out;
    (void)in_sizes; (void)n_in; (void)out_size;

    static int attr_set = 0;
    if (!attr_set) {
        cudaFuncSetAttribute(k_argmin, cudaFuncAttributeMaxDynamicSharedMemorySize, SMEM_BYTES);
        attr_set = 1;
    }

    k_prep  <<<NCODE, 64>>>(e);
    k_znorm <<<256, 256>>>(z);
    k_argmin<<<NTOK / 128, 512, SMEM_BYTES>>>(z);
    cudaMemsetAsync(out + OFF_MINENC, 0, 268435456ULL);
    k_epi   <<<ZSZ / 1024, 256>>>(z, out);
    k_scat  <<<NTOK / 256, 256>>>(out);
    k_fin   <<<1, 1024>>>(out);
}

// round 11
// speedup vs baseline: 15.9881x; 1.1223x over previous
#include <cuda_runtime.h>
#include <cstdint>

#define NTOK   65536
#define DIMC   256
#define NCODE  1024
#define HWSZ   4096
#define ZSZ    16777216
#define OFF_ZQ      1
#define OFF_PERP    16777217
#define OFF_MINENC  16777218ULL
#define OFF_IDX     83886082ULL

#define TOKT 64

// smem byte offsets (dynamic)
#define O_AS    0          // [256 k][64 tok] f32 = 65536
#define O_BS    65536      // 2 x [32 k][256 code] f32 = 65536
#define O_EN    131072     // 1024 f32 = 4096
#define SMEM_BYTES 135168

// ---------------- scratch ----------------
__device__ float  g_et[DIMC * NCODE];     // [c][k]: embed transposed (K-major)
__device__ float  g_en[NCODE];
__device__ float  g_zn[NTOK];
__device__ int    g_idx[NTOK];
__device__ int    g_hist[NCODE];
__device__ double g_loss;

#define CPA16(dst, src) \
    asm volatile("cp.async.cg.shared.global [%0], [%1], 16;" :: "r"(dst), "l"(src))
#define CPA_COMMIT() asm volatile("cp.async.commit_group;")
#define CPA_WAIT(n)  asm volatile("cp.async.wait_group %0;" :: "n"(n))

// ---------------- k_argmin: direct fp32 FFMA GEMM + argmin ----------------
// 256 threads: tx = tid&31 (8 codes -> 256 codes/tile), wp = tid>>5 owns
// 8 tokens. Block = 64 tokens x 1024 codes, K=256 resident in smem.
// 1024 CTAs -> ~6.74 waves at occ1 (3.9% tail vs 18.7% at TOKT=128).
__global__ void __launch_bounds__(256, 1) k_argmin(const float* __restrict__ z) {
    extern __shared__ float sm[];
    float* As = sm;                      // As[k][tok], row 64 floats
    float* Bs = sm + (O_BS >> 2);        // Bs[buf][k][code], row 256 floats
    float* EN = sm + (O_EN >> 2);

    const uint32_t bs_s = (uint32_t)__cvta_generic_to_shared(Bs);

    int tid = threadIdx.x;
    int tx  = tid & 31;
    int wp  = tid >> 5;                  // warp id = token group (8 tokens)
    int n0  = blockIdx.x * TOKT;
    int b   = n0 >> 12, hw0 = n0 & 4095;
    const float* zb = z + (size_t)b * (DIMC * HWSZ) + hw0;

    // ---- prefetch B chunk 0 (ct=0, kc=0): 32 rows x 1KB ----
    {
        const char* src = (const char*)g_et;
#pragma unroll
        for (int j = 0; j < 8; j++) {
            int u = tid + j * 256;               // 2048 x 16B
            int k = u >> 6, c16 = u & 63;
            CPA16(bs_s + (uint32_t)(k * 1024 + c16 * 16),
                  src + (size_t)k * 4096 + c16 * 16);
        }
        CPA_COMMIT();
    }

    // ---- load A tile: As[k][tok] for all 256 dims (coalesced over tok) ----
#pragma unroll
    for (int j = 0; j < 16; j++) {
        int u = tid + j * 256;                   // 4096 float4
        int c = u >> 4, t4 = u & 15;
        float4 v = *(const float4*)(zb + (size_t)c * HWSZ + t4 * 4);
        *(float4*)(As + c * 64 + t4 * 4) = v;
    }
    for (int i = tid; i < NCODE; i += 256) EN[i] = g_en[i];

    // per-thread state: 8 tokens (warp's rows) x 8 codes
    float zn[8];
#pragma unroll
    for (int i = 0; i < 8; i++) zn[i] = g_zn[n0 + wp * 8 + i];
    float bv[8];
    int   bi[8];
#pragma unroll
    for (int i = 0; i < 8; i++) { bv[i] = 3.4e38f; bi[i] = 0; }

    CPA_WAIT(0);
    __syncthreads();

    float acc[8][8];

    for (int m = 0; m < 32; m++) {               // m = ct*8 + kc
        int ct = m >> 3, kc = m & 7, buf = m & 1;

        // prefetch next B chunk
        if (m < 31) {
            int nct = (m + 1) >> 3, nkc = (m + 1) & 7;
            const char* src = (const char*)g_et
                            + (size_t)nkc * 32 * 4096 + (size_t)nct * 1024;
            uint32_t dst = bs_s + (uint32_t)((1 - buf) * 32768);
#pragma unroll
            for (int j = 0; j < 8; j++) {
                int u = tid + j * 256;
                int k = u >> 6, c16 = u & 63;
                CPA16(dst + (uint32_t)(k * 1024 + c16 * 16),
                      src + (size_t)k * 4096 + c16 * 16);
            }
            CPA_COMMIT();
        }

        if (kc == 0) {
#pragma unroll
            for (int i = 0; i < 8; i++)
#pragma unroll
                for (int j = 0; j < 8; j++) acc[i][j] = 0.0f;
        }

        // ---- compute: 32 k-steps, 64 FFMA each ----
        const float* ap = As + kc * 32 * 64 + wp * 8;
        const float* bp = Bs + buf * 8192 + tx * 8;
#pragma unroll 4
        for (int k = 0; k < 32; k++) {
            float a[8], bb[8];
            *(float4*)a        = *(const float4*)(ap + k * 64);      // broadcast
            *(float4*)(a + 4)  = *(const float4*)(ap + k * 64 + 4);
            *(float4*)bb       = *(const float4*)(bp + k * 256);
            *(float4*)(bb + 4) = *(const float4*)(bp + k * 256 + 4);
#pragma unroll
            for (int i = 0; i < 8; i++)
#pragma unroll
                for (int j = 0; j < 8; j++)
                    acc[i][j] = fmaf(a[i], bb[j], acc[i][j]);
        }

        // ---- epilogue at end of each code tile ----
        if (kc == 7) {
#pragma unroll
            for (int j = 0; j < 8; j++) {
                int code = ct * 256 + tx * 8 + j;
                float enj = EN[code];
#pragma unroll
                for (int i = 0; i < 8; i++) {
                    float v = (zn[i] + enj) - 2.0f * acc[i][j];
                    if (v < bv[i]) { bv[i] = v; bi[i] = code; }
                }
            }
        }

        if (m < 31) { CPA_WAIT(1); }
        __syncthreads();
    }

    // ---- warp-level argmin across tx lanes (first-index tie-break) ----
#pragma unroll
    for (int i = 0; i < 8; i++) {
        float v = bv[i];
        int   ix = bi[i];
#pragma unroll
        for (int o = 16; o; o >>= 1) {
            float ov = __shfl_xor_sync(0xffffffffu, v, o);
            int   oi = __shfl_xor_sync(0xffffffffu, ix, o);
            if (ov < v || (ov == v && oi < ix)) { v = ov; ix = oi; }
        }
        if (tx == 0) g_idx[n0 + wp * 8 + i] = ix;
    }
}

// ---------------- |z_n|^2 ----------------
__global__ void k_znorm(const float* __restrict__ z) {
    int b  = blockIdx.x >> 4;
    int hw = ((blockIdx.x & 15) << 8) + threadIdx.x;
    const float* p = z + (size_t)b * DIMC * HWSZ + hw;
    float s = 0.0f;
#pragma unroll 8
    for (int c = 0; c < DIMC; c++) {
        float v = p[(size_t)c * HWSZ];
        s = fmaf(v, v, s);
    }
    g_zn[b * HWSZ + hw] = s;
}

// ---------------- embed prep: transpose + |e|^2 + zero accum ----------------
__global__ void k_prep(const float* __restrict__ e) {
    int k = blockIdx.x;
    int t = threadIdx.x;                       // 64 threads, 4 dims each
    float4 v = ((const float4*)(e + (size_t)k * DIMC))[t];
    int c = t * 4;
    g_et[(c + 0) * NCODE + k] = v.x;
    g_et[(c + 1) * NCODE + k] = v.y;
    g_et[(c + 2) * NCODE + k] = v.z;
    g_et[(c + 3) * NCODE + k] = v.w;
    float s = v.x * v.x + v.y * v.y + v.z * v.z + v.w * v.w;
#pragma unroll
    for (int o = 16; o; o >>= 1) s += __shfl_down_sync(0xffffffffu, s, o);
    __shared__ float sh[2];
    if ((t & 31) == 0) sh[t >> 5] = s;
    __syncthreads();
    if (t == 0) {
        g_en[k]   = sh[0] + sh[1];
        g_hist[k] = 0;
        if (k == 0) g_loss = 0.0;
    }
}

// ---------------- z_q gather + loss + fused one-hot/idx/hist ----------------
__global__ void k_epi(const float* __restrict__ z, float* __restrict__ out) {
    int i4  = blockIdx.x * 256 + threadIdx.x;      // over ZSZ/4
    int hw4 = i4 & 1023;
    int c   = (i4 >> 10) & 255;
    int b   = i4 >> 18;
    int4 kk = *(const int4*)(g_idx + (b << 12) + (hw4 << 2));
    float4 zv = ((const float4*)z)[i4];
    const float* row = g_et + c * NCODE;
    float dx = __ldg(&row[kk.x]) - zv.x;
    float dy = __ldg(&row[kk.y]) - zv.y;
    float dz = __ldg(&row[kk.z]) - zv.z;
    float dw = __ldg(&row[kk.w]) - zv.w;
    size_t o = OFF_ZQ + (size_t)i4 * 4;
    out[o + 0] = zv.x + dx;
    out[o + 1] = zv.y + dy;
    out[o + 2] = zv.z + dz;
    out[o + 3] = zv.w + dw;

    // fused scatter work: one thread slice (c==0) handles its 4 tokens
    if (c == 0) {
        int n = (b << 12) + (hw4 << 2);
        out[OFF_MINENC + (size_t)(n + 0) * NCODE + kk.x] = 1.0f;
        out[OFF_MINENC + (size_t)(n + 1) * NCODE + kk.y] = 1.0f;
        out[OFF_MINENC + (size_t)(n + 2) * NCODE + kk.z] = 1.0f;
        out[OFF_MINENC + (size_t)(n + 3) * NCODE + kk.w] = 1.0f;
        // OFF_IDX is 8-byte aligned only: use float2 stores, not float4
        float* ip = out + OFF_IDX + n;
        *(float2*)(ip)     = make_float2((float)kk.x, (float)kk.y);
        *(float2*)(ip + 2) = make_float2((float)kk.z, (float)kk.w);
        atomicAdd(&g_hist[kk.x], 1);
        atomicAdd(&g_hist[kk.y], 1);
        atomicAdd(&g_hist[kk.z], 1);
        atomicAdd(&g_hist[kk.w], 1);
    }

    float s = dx * dx + dy * dy + dz * dz + dw * dw;
#pragma unroll
    for (int of = 16; of; of >>= 1) s += __shfl_down_sync(0xffffffffu, s, of);
    __shared__ float red[8];
    int t = threadIdx.x;
    if ((t & 31) == 0) red[t >> 5] = s;
    __syncthreads();
    if (t < 8) {
        float w = red[t];
#pragma unroll
        for (int of = 4; of; of >>= 1) w += __shfl_down_sync(0x000000ffu, w, of);
        if (t == 0) atomicAdd(&g_loss, (double)w);
    }
}

// ---------------- finalize ----------------
__global__ void k_fin(float* __restrict__ out) {
    int t = threadIdx.x;
    float em = (float)g_hist[t] * (1.0f / 65536.0f);
    float v = em * logf(em + 1e-10f);
    __shared__ float sh[32];
#pragma unroll
    for (int o = 16; o; o >>= 1) v += __shfl_down_sync(0xffffffffu, v, o);
    if ((t & 31) == 0) sh[t >> 5] = v;
    __syncthreads();
    if (t < 32) {
        float w = sh[t];
#pragma unroll
        for (int o = 16; o; o >>= 1) w += __shfl_down_sync(0xffffffffu, w, o);
        if (t == 0) {
            out[OFF_PERP] = expf(-w);
            out[0] = (float)(g_loss * (1.25 / 16777216.0));
        }
    }
}

// ---------------- launch ----------------
extern "C" void kernel_launch(void* const* d_in, const int* in_sizes, int n_in,
                              void* d_out, int out_size) {
    const float* z = (const float*)d_in[0];
    const float* e = (const float*)d_in[1];
    float* out = (float*)d_out;
    (void)in_sizes; (void)n_in; (void)out_size;

    static int attr_set = 0;
    if (!attr_set) {
        cudaFuncSetAttribute(k_argmin, cudaFuncAttributeMaxDynamicSharedMemorySize, SMEM_BYTES);
        attr_set = 1;
    }

    k_prep  <<<NCODE, 64>>>(e);
    k_znorm <<<256, 256>>>(z);
    k_argmin<<<NTOK / TOKT, 256, SMEM_BYTES>>>(z);
    cudaMemsetAsync(out + OFF_MINENC, 0, 268435456ULL);
    k_epi   <<<ZSZ / 1024, 256>>>(z, out);
    k_fin   <<<1, 1024>>>(out);
}

// round 12
// speedup vs baseline: 16.5021x; 1.0322x over previous
#include <cuda_runtime.h>
#include <cstdint>

#define NTOK   65536
#define DIMC   256
#define NCODE  1024
#define HWSZ   4096
#define ZSZ    16777216
#define OFF_ZQ      1
#define OFF_PERP    16777217
#define OFF_MINENC  16777218ULL
#define OFF_IDX     83886082ULL

#define TOKT 64

// smem byte offsets (dynamic)
#define O_AS    0          // [256 k][64 tok] f32 = 65536
#define O_BS    65536      // 2 x [32 k][256 code] f32 = 65536
#define O_EN    131072     // 1024 f32 = 4096
#define SMEM_BYTES 135168

// ---------------- scratch ----------------
__device__ float  g_et[DIMC * NCODE];     // [c][k]: embed transposed (K-major)
__device__ float  g_en[NCODE];
__device__ float  g_zn[NTOK];
__device__ int    g_idx[NTOK];
__device__ int    g_hist[NCODE];
__device__ double g_loss;

#define CPA16(dst, src) \
    asm volatile("cp.async.cg.shared.global [%0], [%1], 16;" :: "r"(dst), "l"(src))
#define CPA_COMMIT() asm volatile("cp.async.commit_group;")
#define CPA_WAIT(n)  asm volatile("cp.async.wait_group %0;" :: "n"(n))

// ---------------- k_argmin: direct fp32 FFMA GEMM + argmin ----------------
// 256 threads: lanes own two CONTIGUOUS float4 code groups (tx*4 and
// 128+tx*4) -> conflict-free LDS.128 (16B lane stride). wp = tid>>5 owns
// 8 tokens. Block = 64 tokens x 1024 codes, K=256 resident in smem.
__global__ void __launch_bounds__(256, 1) k_argmin(const float* __restrict__ z) {
    extern __shared__ float sm[];
    float* As = sm;                      // As[k][tok], row 64 floats
    float* Bs = sm + (O_BS >> 2);        // Bs[buf][k][code], row 256 floats
    float* EN = sm + (O_EN >> 2);

    const uint32_t bs_s = (uint32_t)__cvta_generic_to_shared(Bs);

    int tid = threadIdx.x;
    int tx  = tid & 31;
    int wp  = tid >> 5;                  // warp id = token group (8 tokens)
    int n0  = blockIdx.x * TOKT;
    int b   = n0 >> 12, hw0 = n0 & 4095;
    const float* zb = z + (size_t)b * (DIMC * HWSZ) + hw0;

    // ---- prefetch B chunk 0 (ct=0, kc=0): 32 rows x 1KB ----
    {
        const char* src = (const char*)g_et;
#pragma unroll
        for (int j = 0; j < 8; j++) {
            int u = tid + j * 256;               // 2048 x 16B
            int k = u >> 6, c16 = u & 63;
            CPA16(bs_s + (uint32_t)(k * 1024 + c16 * 16),
                  src + (size_t)k * 4096 + c16 * 16);
        }
        CPA_COMMIT();
    }

    // ---- load A tile: As[k][tok] for all 256 dims (coalesced over tok) ----
#pragma unroll
    for (int j = 0; j < 16; j++) {
        int u = tid + j * 256;                   // 4096 float4
        int c = u >> 4, t4 = u & 15;
        float4 v = *(const float4*)(zb + (size_t)c * HWSZ + t4 * 4);
        *(float4*)(As + c * 64 + t4 * 4) = v;
    }
    for (int i = tid; i < NCODE; i += 256) EN[i] = g_en[i];

    // per-thread state: 8 tokens (warp's rows) x 8 codes
    float zn[8];
#pragma unroll
    for (int i = 0; i < 8; i++) zn[i] = g_zn[n0 + wp * 8 + i];
    float bv[8];
    int   bi[8];
#pragma unroll
    for (int i = 0; i < 8; i++) { bv[i] = 3.4e38f; bi[i] = 0; }

    CPA_WAIT(0);
    __syncthreads();

    float acc[8][8];

    for (int m = 0; m < 32; m++) {               // m = ct*8 + kc
        int ct = m >> 3, kc = m & 7, buf = m & 1;

        // prefetch next B chunk
        if (m < 31) {
            int nct = (m + 1) >> 3, nkc = (m + 1) & 7;
            const char* src = (const char*)g_et
                            + (size_t)nkc * 32 * 4096 + (size_t)nct * 1024;
            uint32_t dst = bs_s + (uint32_t)((1 - buf) * 32768);
#pragma unroll
            for (int j = 0; j < 8; j++) {
                int u = tid + j * 256;
                int k = u >> 6, c16 = u & 63;
                CPA16(dst + (uint32_t)(k * 1024 + c16 * 16),
                      src + (size_t)k * 4096 + c16 * 16);
            }
            CPA_COMMIT();
        }

        if (kc == 0) {
#pragma unroll
            for (int i = 0; i < 8; i++)
#pragma unroll
                for (int j = 0; j < 8; j++) acc[i][j] = 0.0f;
        }

        // ---- compute: 32 k-steps, 64 FFMA each ----
        const float* ap = As + kc * 32 * 64 + wp * 8;
        const float* bp = Bs + buf * 8192 + tx * 4;     // contiguous lanes
#pragma unroll 4
        for (int k = 0; k < 32; k++) {
            float a[8], bb[8];
            *(float4*)a        = *(const float4*)(ap + k * 64);       // broadcast
            *(float4*)(a + 4)  = *(const float4*)(ap + k * 64 + 4);
            *(float4*)bb       = *(const float4*)(bp + k * 256);        // codes tx*4..+3
            *(float4*)(bb + 4) = *(const float4*)(bp + k * 256 + 128);  // codes 128+tx*4..+3
#pragma unroll
            for (int i = 0; i < 8; i++)
#pragma unroll
                for (int j = 0; j < 8; j++)
                    acc[i][j] = fmaf(a[i], bb[j], acc[i][j]);
        }

        // ---- epilogue at end of each code tile ----
        if (kc == 7) {
#pragma unroll
            for (int j = 0; j < 8; j++) {
                int code = ct * 256 + (j >> 2) * 128 + tx * 4 + (j & 3);
                float enj = EN[code];
#pragma unroll
                for (int i = 0; i < 8; i++) {
                    float v = (zn[i] + enj) - 2.0f * acc[i][j];
                    if (v < bv[i]) { bv[i] = v; bi[i] = code; }
                }
            }
        }

        if (m < 31) { CPA_WAIT(1); }
        __syncthreads();
    }

    // ---- warp-level argmin across tx lanes (first-index tie-break) ----
#pragma unroll
    for (int i = 0; i < 8; i++) {
        float v = bv[i];
        int   ix = bi[i];
#pragma unroll
        for (int o = 16; o; o >>= 1) {
            float ov = __shfl_xor_sync(0xffffffffu, v, o);
            int   oi = __shfl_xor_sync(0xffffffffu, ix, o);
            if (ov < v || (ov == v && oi < ix)) { v = ov; ix = oi; }
        }
        if (tx == 0) g_idx[n0 + wp * 8 + i] = ix;
    }
}

// ---------------- |z_n|^2 ----------------
__global__ void k_znorm(const float* __restrict__ z) {
    int b  = blockIdx.x >> 4;
    int hw = ((blockIdx.x & 15) << 8) + threadIdx.x;
    const float* p = z + (size_t)b * DIMC * HWSZ + hw;
    float s = 0.0f;
#pragma unroll 8
    for (int c = 0; c < DIMC; c++) {
        float v = p[(size_t)c * HWSZ];
        s = fmaf(v, v, s);
    }
    g_zn[b * HWSZ + hw] = s;
}

// ---------------- embed prep: transpose + |e|^2 + zero accum ----------------
__global__ void k_prep(const float* __restrict__ e) {
    int k = blockIdx.x;
    int t = threadIdx.x;                       // 64 threads, 4 dims each
    float4 v = ((const float4*)(e + (size_t)k * DIMC))[t];
    int c = t * 4;
    g_et[(c + 0) * NCODE + k] = v.x;
    g_et[(c + 1) * NCODE + k] = v.y;
    g_et[(c + 2) * NCODE + k] = v.z;
    g_et[(c + 3) * NCODE + k] = v.w;
    float s = v.x * v.x + v.y * v.y + v.z * v.z + v.w * v.w;
#pragma unroll
    for (int o = 16; o; o >>= 1) s += __shfl_down_sync(0xffffffffu, s, o);
    __shared__ float sh[2];
    if ((t & 31) == 0) sh[t >> 5] = s;
    __syncthreads();
    if (t == 0) {
        g_en[k]   = sh[0] + sh[1];
        g_hist[k] = 0;
        if (k == 0) g_loss = 0.0;
    }
}

// ---------------- z_q gather + loss + fused one-hot/idx/hist ----------------
__global__ void k_epi(const float* __restrict__ z, float* __restrict__ out) {
    int i4  = blockIdx.x * 256 + threadIdx.x;      // over ZSZ/4
    int hw4 = i4 & 1023;
    int c   = (i4 >> 10) & 255;
    int b   = i4 >> 18;
    int4 kk = *(const int4*)(g_idx + (b << 12) + (hw4 << 2));
    float4 zv = ((const float4*)z)[i4];
    const float* row = g_et + c * NCODE;
    float dx = __ldg(&row[kk.x]) - zv.x;
    float dy = __ldg(&row[kk.y]) - zv.y;
    float dz = __ldg(&row[kk.z]) - zv.z;
    float dw = __ldg(&row[kk.w]) - zv.w;
    size_t o = OFF_ZQ + (size_t)i4 * 4;
    out[o + 0] = zv.x + dx;
    out[o + 1] = zv.y + dy;
    out[o + 2] = zv.z + dz;
    out[o + 3] = zv.w + dw;

    // fused scatter work: one thread slice (c==0) handles its 4 tokens
    if (c == 0) {
        int n = (b << 12) + (hw4 << 2);
        out[OFF_MINENC + (size_t)(n + 0) * NCODE + kk.x] = 1.0f;
        out[OFF_MINENC + (size_t)(n + 1) * NCODE + kk.y] = 1.0f;
        out[OFF_MINENC + (size_t)(n + 2) * NCODE + kk.z] = 1.0f;
        out[OFF_MINENC + (size_t)(n + 3) * NCODE + kk.w] = 1.0f;
        // OFF_IDX is 8-byte aligned only: use float2 stores, not float4
        float* ip = out + OFF_IDX + n;
        *(float2*)(ip)     = make_float2((float)kk.x, (float)kk.y);
        *(float2*)(ip + 2) = make_float2((float)kk.z, (float)kk.w);
        atomicAdd(&g_hist[kk.x], 1);
        atomicAdd(&g_hist[kk.y], 1);
        atomicAdd(&g_hist[kk.z], 1);
        atomicAdd(&g_hist[kk.w], 1);
    }

    float s = dx * dx + dy * dy + dz * dz + dw * dw;
#pragma unroll
    for (int of = 16; of; of >>= 1) s += __shfl_down_sync(0xffffffffu, s, of);
    __shared__ float red[8];
    int t = threadIdx.x;
    if ((t & 31) == 0) red[t >> 5] = s;
    __syncthreads();
    if (t < 8) {
        float w = red[t];
#pragma unroll
        for (int of = 4; of; of >>= 1) w += __shfl_down_sync(0x000000ffu, w, of);
        if (t == 0) atomicAdd(&g_loss, (double)w);
    }
}

// ---------------- finalize ----------------
__global__ void k_fin(float* __restrict__ out) {
    int t = threadIdx.x;
    float em = (float)g_hist[t] * (1.0f / 65536.0f);
    float v = em * logf(em + 1e-10f);
    __shared__ float sh[32];
#pragma unroll
    for (int o = 16; o; o >>= 1) v += __shfl_down_sync(0xffffffffu, v, o);
    if ((t & 31) == 0) sh[t >> 5] = v;
    __syncthreads();
    if (t < 32) {
        float w = sh[t];
#pragma unroll
        for (int o = 16; o; o >>= 1) w += __shfl_down_sync(0xffffffffu, w, o);
        if (t == 0) {
            out[OFF_PERP] = expf(-w);
            out[0] = (float)(g_loss * (1.25 / 16777216.0));
        }
    }
}

// ---------------- launch ----------------
extern "C" void kernel_launch(void* const* d_in, const int* in_sizes, int n_in,
                              void* d_out, int out_size) {
    const float* z = (const float*)d_in[0];
    const float* e = (const float*)d_in[1];
    float* out = (float*)d_out;
    (void)in_sizes; (void)n_in; (void)out_size;

    static int attr_set = 0;
    if (!attr_set) {
        cudaFuncSetAttribute(k_argmin, cudaFuncAttributeMaxDynamicSharedMemorySize, SMEM_BYTES);
        attr_set = 1;
    }

    k_prep  <<<NCODE, 64>>>(e);
    k_znorm <<<256, 256>>>(z);
    k_argmin<<<NTOK / TOKT, 256, SMEM_BYTES>>>(z);
    cudaMemsetAsync(out + OFF_MINENC, 0, 268435456ULL);
    k_epi   <<<ZSZ / 1024, 256>>>(z, out);
    k_fin   <<<1, 1024>>>(out);
}